// round 4
// baseline (speedup 1.0000x reference)
#include <cuda_runtime.h>
#include <cstdint>

#define B_   64
#define T_   2048
#define DZ_  512
#define DC_  256
#define K_   12
#define R_   2
#define KO_  (K_ * DZ_)     // 6144

// score kernel tiling
#define RPB  256            // t' rows per block
#define SDK  16             // d floats per pipeline stage
#define NSTG (DZ_ / SDK)    // 32 stages
#define PF4  5              // smem row pitch in float4 (80 B -> conflict-free LDS.128)
#define STAGE_F4 (RPB * PF4)
#define SCORE_SMEM (KO_ * 4 + 2 * STAGE_F4 * 16)   // 24576 + 40960 = 65536 B

// pred kernel: row-major tiles, pitch 260 floats (conflict-free LDS.64 reads)
#define PITCH 260
#define PRED_SMEM (2 * 64 * PITCH * 4)             // 133120 B

// ---- scratch (static device allocations; no cudaMalloc allowed) ----
__device__ __align__(16) float g_pred[B_ * KO_];   // [b][k*Dz+o]
__device__ __align__(16) float g_s[K_ * B_ * T_];  // [k][b][t']
__device__ unsigned long long g_acc;               // Q32.32 fixed-point loss accum
__device__ int g_cnt;

extern __shared__ __align__(16) float smem_dyn[];

static __device__ __forceinline__ unsigned smem_u32(const void* p) {
    return (unsigned)__cvta_generic_to_shared(p);
}
static __device__ __forceinline__ float u64lo(unsigned long long v) {
    return __uint_as_float((unsigned)(v & 0xffffffffu));
}
static __device__ __forceinline__ float u64hi(unsigned long long v) {
    return __uint_as_float((unsigned)(v >> 32));
}

// ============================================================================
// Kernel A: pred[b][ko] = sum_d c[b, t[b], d] * W[ko][d] + bias[ko]
// GEMM 64 x 6144 x 256. Row-major smem (no transpose), FFMA2 packed along d
// (acc = (even-d, odd-d) partials, one horizontal add at the end).
// grid = 96 blocks (64 ko each), 128 threads, micro-tile 4b x 8ko.
// ============================================================================
__global__ __launch_bounds__(128, 1) void pred_kernel(const float* __restrict__ c,
                                                      const float* __restrict__ W,
                                                      const float* __restrict__ bias,
                                                      const int*   __restrict__ t) {
    float* cts = smem_dyn;                 // [64 b ][PITCH]
    float* ws  = smem_dyn + 64 * PITCH;    // [64 ko][PITCH]
    __shared__ int ts[B_];

    int tid = threadIdx.x;
    if (blockIdx.x == 0 && tid == 0) { g_acc = 0ULL; g_cnt = 0; }
    if (tid < B_) ts[tid] = t[tid];
    __syncthreads();

    int ko0 = blockIdx.x * 64;

    // coalesced loads, contiguous conflict-free STS.128
    #pragma unroll
    for (int i = 0; i < 32; i++) {
        int f = i * 128 + tid;
        int r = f >> 6, c4 = f & 63;
        float4 v = *(const float4*)(c + ((long)r * T_ + ts[r]) * DC_ + c4 * 4);
        *(float4*)(cts + r * PITCH + c4 * 4) = v;
        float4 wv4 = *(const float4*)(W + (long)(ko0 + r) * DC_ + c4 * 4);
        *(float4*)(ws + r * PITCH + c4 * 4) = wv4;
    }
    __syncthreads();

    int tx = tid & 7, ty = tid >> 3;       // tx: ko lane (8), ty: b lane (16)

    unsigned long long acc[4][8];
    #pragma unroll
    for (int i = 0; i < 4; i++)
        #pragma unroll
        for (int j = 0; j < 8; j++) acc[i][j] = 0ULL;

    #pragma unroll 4
    for (int d = 0; d < DC_; d += 2) {
        unsigned long long cv[4], wv[8];
        #pragma unroll
        for (int i = 0; i < 4; i++)
            cv[i] = *(const unsigned long long*)(cts + (ty + 16 * i) * PITCH + d);
        #pragma unroll
        for (int j = 0; j < 8; j++)
            wv[j] = *(const unsigned long long*)(ws + (tx + 8 * j) * PITCH + d);
        #pragma unroll
        for (int i = 0; i < 4; i++)
            #pragma unroll
            for (int j = 0; j < 8; j++)
                asm("fma.rn.f32x2 %0, %1, %2, %0;"
                    : "+l"(acc[i][j]) : "l"(cv[i]), "l"(wv[j]));
    }

    float wb[8];
    #pragma unroll
    for (int j = 0; j < 8; j++) wb[j] = bias[ko0 + tx + 8 * j];

    #pragma unroll
    for (int i = 0; i < 4; i++) {
        int b = ty + 16 * i;
        #pragma unroll
        for (int j = 0; j < 8; j++) {
            int ko = ko0 + tx + 8 * j;
            g_pred[(long)b * KO_ + ko] = u64lo(acc[i][j]) + u64hi(acc[i][j]) + wb[j];
        }
    }
}

// ============================================================================
// Kernel B (hot): s[k][b][t'] = dot(z[b,t',:], pred[b,k,:])
// z (268 MB) streamed once via 16B cp.async.cg double buffer, pitch-5-float4
// rows. 2 rows/thread, FFMA2. grid = (T/256, B) = 512 blocks, 3 blocks/SM.
// ============================================================================
__global__ __launch_bounds__(128, 3) void score_kernel(const float* __restrict__ z) {
    float*  preds = smem_dyn;                        // 6144 floats
    float4* zbuf  = (float4*)(smem_dyn + KO_);       // 2 x (256*5) float4

    const int tid  = threadIdx.x;
    const int b    = blockIdx.y;
    const int t0   = blockIdx.x * RPB;
    const int l    = tid & 31, w = tid >> 5;
    const int base = w * 64;

    const float* zb = z + ((long)b * T_ + t0) * DZ_;

    auto load_stage = [&](int s, int bufsel) {
        unsigned sb = smem_u32(zbuf + bufsel * STAGE_F4);
        const float* gs = zb + s * SDK;
        #pragma unroll
        for (int j = 0; j < 8; j++) {
            int f = tid + j * 128;                   // 0..1023 float4 slots
            int r = f >> 2, cc = f & 3;
            unsigned sa = sb + (unsigned)((r * PF4 + cc) * 16);
            const float* ga = gs + (long)r * DZ_ + cc * 4;
            asm volatile("cp.async.cg.shared.global [%0], [%1], 16;\n"
                         :: "r"(sa), "l"(ga));
        }
        asm volatile("cp.async.commit_group;\n");
    };

    load_stage(0, 0);
    load_stage(1, 1);

    // stage this b's 12 pred vectors
    const float4* gp = (const float4*)(g_pred + (long)b * KO_);
    float4* sp = (float4*)preds;
    #pragma unroll
    for (int i = 0; i < KO_ / 4 / 128; i++) sp[tid + i * 128] = gp[tid + i * 128];

    unsigned long long acc[2][K_];
    #pragma unroll
    for (int i = 0; i < 2; i++)
        #pragma unroll
        for (int k = 0; k < K_; k++) acc[i][k] = 0ULL;

    for (int s = 0; s < NSTG; s++) {
        if (s < NSTG - 1) asm volatile("cp.async.wait_group 1;\n");
        else              asm volatile("cp.async.wait_group 0;\n");
        __syncthreads();

        const float4* zc = zbuf + (s & 1) * STAGE_F4;
        #pragma unroll
        for (int c4 = 0; c4 < 4; c4++) {
            ulonglong2 zz[2];
            #pragma unroll
            for (int i = 0; i < 2; i++)
                zz[i] = *(const ulonglong2*)(zc + (base + 32 * i + l) * PF4 + c4);
            #pragma unroll
            for (int k = 0; k < K_; k++) {
                ulonglong2 p = *(const ulonglong2*)(preds + k * DZ_ + s * SDK + c4 * 4);
                #pragma unroll
                for (int i = 0; i < 2; i++) {
                    asm("fma.rn.f32x2 %0, %1, %2, %0;"
                        : "+l"(acc[i][k]) : "l"(zz[i].x), "l"(p.x));
                    asm("fma.rn.f32x2 %0, %1, %2, %0;"
                        : "+l"(acc[i][k]) : "l"(zz[i].y), "l"(p.y));
                }
            }
        }
        __syncthreads();
        if (s + 2 < NSTG) load_stage(s + 2, s & 1);
    }

    #pragma unroll
    for (int i = 0; i < 2; i++) {
        int row = t0 + base + 32 * i + l;
        #pragma unroll
        for (int k = 0; k < K_; k++)
            g_s[((long)k * B_ + b) * T_ + row] = u64lo(acc[i][k]) + u64hi(acc[i][k]);
    }
}

// ============================================================================
// Kernel C: per (k,b): pos + 2 replicates of 2047 sampled negatives ->
// mean logsumexp. Q32.32 integer atomic finale (deterministic).
// grid = 768 blocks, 256 threads.
// ============================================================================
__global__ __launch_bounds__(256) void loss_kernel(const int* __restrict__ t,
                                                   const int* __restrict__ ridx_g,
                                                   float* __restrict__ out) {
    __shared__ float srow[T_];
    __shared__ float red[8];

    int tid = threadIdx.x;
    int kb  = blockIdx.x;
    int k = kb >> 6, b = kb & 63;           // kb = k*B + b
    int lane = tid & 31, wid = tid >> 5;

    const float* src = g_s + (long)kb * T_;
    for (int i = tid; i < T_; i += 256) srow[i] = src[i];
    __syncthreads();

    int e = t[b] + k + 1;
    float pos = srow[e];
    float lse_sum = 0.f;

    for (int r = 0; r < R_; r++) {
        const int* ridx = ridx_g + (k * R_ + r) * (T_ - 1);
        float v[8];
        float m = pos;
        #pragma unroll
        for (int it = 0; it < 8; it++) {
            int i = tid + it * 256;
            float x = -3.0e38f;
            if (i < T_ - 1) {
                int j = ridx[i];
                j += (j >= e);              // skip the positive frame
                x = srow[j];
            }
            v[it] = x;
            m = fmaxf(m, x);
        }
        #pragma unroll
        for (int o = 16; o; o >>= 1) m = fmaxf(m, __shfl_xor_sync(0xffffffffu, m, o));
        if (lane == 0) red[wid] = m;
        __syncthreads();
        float mm = red[0];
        #pragma unroll
        for (int j = 1; j < 8; j++) mm = fmaxf(mm, red[j]);
        __syncthreads();

        float sacc = (tid == 0) ? expf(pos - mm) : 0.f;
        #pragma unroll
        for (int it = 0; it < 8; it++)
            if (tid + it * 256 < T_ - 1) sacc += expf(v[it] - mm);
        #pragma unroll
        for (int o = 16; o; o >>= 1) sacc += __shfl_xor_sync(0xffffffffu, sacc, o);
        if (lane == 0) red[wid] = sacc;
        __syncthreads();
        float ss = red[0];
        #pragma unroll
        for (int j = 1; j < 8; j++) ss += red[j];
        __syncthreads();

        lse_sum += mm + logf(ss);
    }

    if (tid == 0) {
        double vkb = (double)lse_sum / (double)R_ - (double)pos;   // >= 0
        long long q = __double2ll_rn(vkb * 4294967296.0);
        atomicAdd(&g_acc, (unsigned long long)q);
        __threadfence();
        if (atomicAdd(&g_cnt, 1) == K_ * B_ - 1) {
            unsigned long long tot = atomicAdd(&g_acc, 0ULL);
            out[0] = (float)((double)(long long)tot / 4294967296.0
                             / (double)(K_ * B_));
        }
    }
}

// ============================================================================
extern "C" void kernel_launch(void* const* d_in, const int* in_sizes, int n_in,
                              void* d_out, int out_size) {
    const float* z        = (const float*)d_in[0];
    const float* c        = (const float*)d_in[1];
    const float* Wk_w     = (const float*)d_in[2];
    const float* Wk_b     = (const float*)d_in[3];
    const int*   t        = (const int*)d_in[4];
    const int*   rand_idx = (const int*)d_in[5];

    cudaFuncSetAttribute(pred_kernel,
                         cudaFuncAttributeMaxDynamicSharedMemorySize, PRED_SMEM);
    cudaFuncSetAttribute(score_kernel,
                         cudaFuncAttributeMaxDynamicSharedMemorySize, SCORE_SMEM);

    pred_kernel<<<KO_ / 64, 128, PRED_SMEM>>>(c, Wk_w, Wk_b, t);
    score_kernel<<<dim3(T_ / RPB, B_), 128, SCORE_SMEM>>>(z);
    loss_kernel<<<K_ * B_, 256>>>(t, rand_idx, (float*)d_out);
}

// round 5
// speedup vs baseline: 1.0253x; 1.0253x over previous
#include <cuda_runtime.h>
#include <cstdint>

#define B_   64
#define T_   2048
#define DZ_  512
#define DC_  256
#define K_   12
#define R_   2
#define KO_  (K_ * DZ_)     // 6144

// score kernel tiling (unchanged from R4 best)
#define RPB  256            // t' rows per block
#define SDK  16             // d floats per pipeline stage
#define NSTG (DZ_ / SDK)    // 32 stages
#define PF4  5              // smem row pitch in float4 (80 B -> conflict-free LDS.128)
#define STAGE_F4 (RPB * PF4)
#define SCORE_SMEM (KO_ * 4 + 2 * STAGE_F4 * 16)   // 65536 B -> 3 blocks/SM

// pred kernel: 32-ko tiles, 256 threads, 2 blocks/SM (16 warps/SM)
#define PITCH 260
#define KOT   32
#define PRED_SMEM ((64 + KOT) * PITCH * 4)         // 99840 B

// ---- scratch (static device allocations; no cudaMalloc allowed) ----
__device__ __align__(16) float g_pred[B_ * KO_];   // [b][k*Dz+o]
__device__ __align__(16) float g_s[K_ * B_ * T_];  // [k][b][t']
__device__ unsigned long long g_acc;               // Q32.32 fixed-point loss accum
__device__ int g_cnt;

extern __shared__ __align__(16) float smem_dyn[];

static __device__ __forceinline__ unsigned smem_u32(const void* p) {
    return (unsigned)__cvta_generic_to_shared(p);
}
static __device__ __forceinline__ float u64lo(unsigned long long v) {
    return __uint_as_float((unsigned)(v & 0xffffffffu));
}
static __device__ __forceinline__ float u64hi(unsigned long long v) {
    return __uint_as_float((unsigned)(v >> 32));
}

// ============================================================================
// Kernel A: pred[b][ko] = sum_d c[b, t[b], d] * W[ko][d] + bias[ko]
// GEMM 64 x 6144 x 256. Row-major smem, FFMA2 packed along d.
// grid = 192 blocks (32 ko each), 256 threads, micro 2b x 4ko,
// 2 blocks/SM -> 4 warps/SMSP (latency hidden), one wave on 96 SMs.
// ============================================================================
__global__ __launch_bounds__(256, 2) void pred_kernel(const float* __restrict__ c,
                                                      const float* __restrict__ W,
                                                      const float* __restrict__ bias,
                                                      const int*   __restrict__ t) {
    float* cts = smem_dyn;                 // [64 b ][PITCH]
    float* ws  = smem_dyn + 64 * PITCH;    // [32 ko][PITCH]
    __shared__ int ts[B_];

    int tid = threadIdx.x;
    if (blockIdx.x == 0 && tid == 0) { g_acc = 0ULL; g_cnt = 0; }
    if (tid < B_) ts[tid] = t[tid];
    __syncthreads();

    int ko0 = blockIdx.x * KOT;

    // coalesced loads, contiguous conflict-free STS.128
    #pragma unroll
    for (int i = 0; i < 16; i++) {         // c tile: 64 rows x 64 float4
        int f = i * 256 + tid;
        int r = f >> 6, c4 = f & 63;
        float4 v = *(const float4*)(c + ((long)r * T_ + ts[r]) * DC_ + c4 * 4);
        *(float4*)(cts + r * PITCH + c4 * 4) = v;
    }
    #pragma unroll
    for (int i = 0; i < 8; i++) {          // W tile: 32 rows x 64 float4
        int f = i * 256 + tid;
        int r = f >> 6, c4 = f & 63;
        float4 wv4 = *(const float4*)(W + (long)(ko0 + r) * DC_ + c4 * 4);
        *(float4*)(ws + r * PITCH + c4 * 4) = wv4;
    }
    __syncthreads();

    int tx = tid & 7, ty = tid >> 3;       // tx: ko lane (8), ty: b lane (32)

    unsigned long long acc[2][4];
    #pragma unroll
    for (int i = 0; i < 2; i++)
        #pragma unroll
        for (int j = 0; j < 4; j++) acc[i][j] = 0ULL;

    #pragma unroll 8
    for (int d = 0; d < DC_; d += 2) {
        unsigned long long cv[2], wv[4];
        #pragma unroll
        for (int i = 0; i < 2; i++)
            cv[i] = *(const unsigned long long*)(cts + (ty + 32 * i) * PITCH + d);
        #pragma unroll
        for (int j = 0; j < 4; j++)
            wv[j] = *(const unsigned long long*)(ws + (tx + 8 * j) * PITCH + d);
        #pragma unroll
        for (int i = 0; i < 2; i++)
            #pragma unroll
            for (int j = 0; j < 4; j++)
                asm("fma.rn.f32x2 %0, %1, %2, %0;"
                    : "+l"(acc[i][j]) : "l"(cv[i]), "l"(wv[j]));
    }

    #pragma unroll
    for (int i = 0; i < 2; i++) {
        int b = ty + 32 * i;
        #pragma unroll
        for (int j = 0; j < 4; j++) {
            int ko = ko0 + tx + 8 * j;
            g_pred[(long)b * KO_ + ko] =
                u64lo(acc[i][j]) + u64hi(acc[i][j]) + bias[ko];
        }
    }
}

// ============================================================================
// Kernel B (hot): s[k][b][t'] = dot(z[b,t',:], pred[b,k,:])
// z (268 MB) streamed once via 16B cp.async.cg double buffer, pitch-5-float4
// rows. 2 rows/thread, FFMA2. grid = (T/256, B) = 512 blocks, 3 blocks/SM.
// ============================================================================
__global__ __launch_bounds__(128, 3) void score_kernel(const float* __restrict__ z) {
    float*  preds = smem_dyn;                        // 6144 floats
    float4* zbuf  = (float4*)(smem_dyn + KO_);       // 2 x (256*5) float4

    const int tid  = threadIdx.x;
    const int b    = blockIdx.y;
    const int t0   = blockIdx.x * RPB;
    const int l    = tid & 31, w = tid >> 5;
    const int base = w * 64;

    const float* zb = z + ((long)b * T_ + t0) * DZ_;

    auto load_stage = [&](int s, int bufsel) {
        unsigned sb = smem_u32(zbuf + bufsel * STAGE_F4);
        const float* gs = zb + s * SDK;
        #pragma unroll
        for (int j = 0; j < 8; j++) {
            int f = tid + j * 128;                   // 0..1023 float4 slots
            int r = f >> 2, cc = f & 3;
            unsigned sa = sb + (unsigned)((r * PF4 + cc) * 16);
            const float* ga = gs + (long)r * DZ_ + cc * 4;
            asm volatile("cp.async.cg.shared.global [%0], [%1], 16;\n"
                         :: "r"(sa), "l"(ga));
        }
        asm volatile("cp.async.commit_group;\n");
    };

    load_stage(0, 0);
    load_stage(1, 1);

    // stage this b's 12 pred vectors
    const float4* gp = (const float4*)(g_pred + (long)b * KO_);
    float4* sp = (float4*)preds;
    #pragma unroll
    for (int i = 0; i < KO_ / 4 / 128; i++) sp[tid + i * 128] = gp[tid + i * 128];

    unsigned long long acc[2][K_];
    #pragma unroll
    for (int i = 0; i < 2; i++)
        #pragma unroll
        for (int k = 0; k < K_; k++) acc[i][k] = 0ULL;

    for (int s = 0; s < NSTG; s++) {
        if (s < NSTG - 1) asm volatile("cp.async.wait_group 1;\n");
        else              asm volatile("cp.async.wait_group 0;\n");
        __syncthreads();

        const float4* zc = zbuf + (s & 1) * STAGE_F4;
        #pragma unroll
        for (int c4 = 0; c4 < 4; c4++) {
            ulonglong2 zz[2];
            #pragma unroll
            for (int i = 0; i < 2; i++)
                zz[i] = *(const ulonglong2*)(zc + (base + 32 * i + l) * PF4 + c4);
            #pragma unroll
            for (int k = 0; k < K_; k++) {
                ulonglong2 p = *(const ulonglong2*)(preds + k * DZ_ + s * SDK + c4 * 4);
                #pragma unroll
                for (int i = 0; i < 2; i++) {
                    asm("fma.rn.f32x2 %0, %1, %2, %0;"
                        : "+l"(acc[i][k]) : "l"(zz[i].x), "l"(p.x));
                    asm("fma.rn.f32x2 %0, %1, %2, %0;"
                        : "+l"(acc[i][k]) : "l"(zz[i].y), "l"(p.y));
                }
            }
        }
        __syncthreads();
        if (s + 2 < NSTG) load_stage(s + 2, s & 1);
    }

    #pragma unroll
    for (int i = 0; i < 2; i++) {
        int row = t0 + base + 32 * i + l;
        #pragma unroll
        for (int k = 0; k < K_; k++)
            g_s[((long)k * B_ + b) * T_ + row] = u64lo(acc[i][k]) + u64hi(acc[i][k]);
    }
}

// ============================================================================
// Kernel C: per (k,b): pos + 2 replicates of 2047 sampled negatives ->
// mean logsumexp. 512 threads; Q32.32 integer atomic finale (deterministic).
// grid = 768 blocks.
// ============================================================================
__global__ __launch_bounds__(512) void loss_kernel(const int* __restrict__ t,
                                                   const int* __restrict__ ridx_g,
                                                   float* __restrict__ out) {
    __shared__ float srow[T_];
    __shared__ float red[16];

    int tid = threadIdx.x;
    int kb  = blockIdx.x;
    int k = kb >> 6, b = kb & 63;           // kb = k*B + b
    int lane = tid & 31, wid = tid >> 5;

    const float* src = g_s + (long)kb * T_;
    #pragma unroll
    for (int i = 0; i < 4; i++) srow[tid + i * 512] = src[tid + i * 512];
    __syncthreads();

    int e = t[b] + k + 1;
    float pos = srow[e];
    float lse_sum = 0.f;

    for (int r = 0; r < R_; r++) {
        const int* ridx = ridx_g + (k * R_ + r) * (T_ - 1);
        float v[4];
        float m = pos;
        #pragma unroll
        for (int it = 0; it < 4; it++) {
            int i = tid + it * 512;
            float x = -3.0e38f;
            if (i < T_ - 1) {
                int j = ridx[i];
                j += (j >= e);              // skip the positive frame
                x = srow[j];
            }
            v[it] = x;
            m = fmaxf(m, x);
        }
        #pragma unroll
        for (int o = 16; o; o >>= 1) m = fmaxf(m, __shfl_xor_sync(0xffffffffu, m, o));
        if (lane == 0) red[wid] = m;
        __syncthreads();
        float mm = red[0];
        #pragma unroll
        for (int j = 1; j < 16; j++) mm = fmaxf(mm, red[j]);
        __syncthreads();

        float sacc = (tid == 0) ? expf(pos - mm) : 0.f;
        #pragma unroll
        for (int it = 0; it < 4; it++)
            if (tid + it * 512 < T_ - 1) sacc += expf(v[it] - mm);
        #pragma unroll
        for (int o = 16; o; o >>= 1) sacc += __shfl_xor_sync(0xffffffffu, sacc, o);
        if (lane == 0) red[wid] = sacc;
        __syncthreads();
        float ss = red[0];
        #pragma unroll
        for (int j = 1; j < 16; j++) ss += red[j];
        __syncthreads();

        lse_sum += mm + logf(ss);
    }

    if (tid == 0) {
        double vkb = (double)lse_sum / (double)R_ - (double)pos;   // >= 0
        long long q = __double2ll_rn(vkb * 4294967296.0);
        atomicAdd(&g_acc, (unsigned long long)q);
        __threadfence();
        if (atomicAdd(&g_cnt, 1) == K_ * B_ - 1) {
            unsigned long long tot = atomicAdd(&g_acc, 0ULL);
            out[0] = (float)((double)(long long)tot / 4294967296.0
                             / (double)(K_ * B_));
        }
    }
}

// ============================================================================
extern "C" void kernel_launch(void* const* d_in, const int* in_sizes, int n_in,
                              void* d_out, int out_size) {
    const float* z        = (const float*)d_in[0];
    const float* c        = (const float*)d_in[1];
    const float* Wk_w     = (const float*)d_in[2];
    const float* Wk_b     = (const float*)d_in[3];
    const int*   t        = (const int*)d_in[4];
    const int*   rand_idx = (const int*)d_in[5];

    cudaFuncSetAttribute(pred_kernel,
                         cudaFuncAttributeMaxDynamicSharedMemorySize, PRED_SMEM);
    cudaFuncSetAttribute(score_kernel,
                         cudaFuncAttributeMaxDynamicSharedMemorySize, SCORE_SMEM);

    pred_kernel<<<KO_ / KOT, 256, PRED_SMEM>>>(c, Wk_w, Wk_b, t);
    score_kernel<<<dim3(T_ / RPB, B_), 128, SCORE_SMEM>>>(z);
    loss_kernel<<<K_ * B_, 512>>>(t, rand_idx, (float*)d_out);
}